// round 8
// baseline (speedup 1.0000x reference)
#include <cuda_runtime.h>
#include <math.h>

#define NTHREADS 256
#define HD 512
#define NPT 2          // neurons per thread
#define NC 23          // channels: 1 value + 8 tangents + 14 second-order
#define CP 24          // padded channel stride (doubles)
#define KT 16          // k-tile for W staging
#define WPAD 17        // padded wtile row (conflict-free reads)
#define NP 14          // second-order pair channels
#define LN_EPS 1e-5

// double-precision block reduction over the CTA (N channels)
template<int N>
__device__ __forceinline__ void block_reduce_d(const double (&p)[N], double* red, double* wsum, int tid){
    int lane = tid & 31, w = tid >> 5;
    #pragma unroll
    for (int q = 0; q < N; q++){
        double v = p[q];
        v += __shfl_down_sync(0xffffffffu, v, 16);
        v += __shfl_down_sync(0xffffffffu, v, 8);
        v += __shfl_down_sync(0xffffffffu, v, 4);
        v += __shfl_down_sync(0xffffffffu, v, 2);
        v += __shfl_down_sync(0xffffffffu, v, 1);
        if (lane == 0) wsum[w*CP + q] = v;
    }
    __syncthreads();
    if (tid < N){
        double s = 0.0;
        #pragma unroll
        for (int w2 = 0; w2 < NTHREADS/32; w2++) s += wsum[w2*CP + tid];
        red[tid] = s;
    }
    __syncthreads();
}

// softplus jet, full double: a = softplus(z), adot = sigma*zdot,
// addot = sigma' zdot_a zdot_b + sigma zddot
__device__ __forceinline__ void softplus_stage(double& v, double t[8], double u[NP], const double qd[4]){
    const int PA[NP] = {4,4,4,4,5,5,5,6,6,7, 8,8,8,8};   // 8 == direction d = sum qd_j e_j (q-slots)
    const int PB[NP] = {4,5,6,7,5,6,7,6,7,7, 4,5,6,7};
    double z   = v;
    double ezn = exp(-fabs(z));
    double sg  = (z >= 0.0) ? 1.0/(1.0 + ezn) : ezn/(1.0 + ezn);
    double sp  = fmax(z, 0.0) + log1p(ezn);
    double spp = sg*(1.0 - sg);
    double td  = qd[0]*t[0] + qd[1]*t[1] + qd[2]*t[2] + qd[3]*t[3];
    #pragma unroll
    for (int pp = 0; pp < NP; pp++){
        double ta = (PA[pp] == 8) ? td : t[PA[pp]];
        u[pp] = spp*ta*t[PB[pp]] + sg*u[pp];
    }
    #pragma unroll
    for (int i = 0; i < 8; i++) t[i] = sg*t[i];
    v = sp;
}

// LayerNorm jet across the 512 neurons of the CTA's sample — full double
__device__ __forceinline__ void ln_stage(
    double av[NPT], double at[NPT][8], double au[NPT][NP],
    const float* __restrict__ g, const float* __restrict__ be,
    const double qd[4], double* red, double* red2, double* wsum, int tid)
{
    const int PA[NP] = {4,4,4,4,5,5,5,6,6,7, 8,8,8,8};
    const int PB[NP] = {4,5,6,7,5,6,7,6,7,7, 4,5,6,7};
    const double inv = 1.0/(double)HD;

    // pass A: means of a, adot_i, addot_p
    double p[NC];
    p[0] = av[0] + av[1];
    #pragma unroll
    for (int i = 0; i < 8; i++)  p[1+i] = at[0][i] + at[1][i];
    #pragma unroll
    for (int pp = 0; pp < NP; pp++) p[9+pp] = au[0][pp] + au[1][pp];
    block_reduce_d<NC>(p, red, wsum, tid);

    // center
    double ctd[NPT];
    double m = red[0]*inv;
    #pragma unroll
    for (int j = 0; j < NPT; j++){
        av[j] -= m;
        #pragma unroll
        for (int i = 0; i < 8; i++)  at[j][i] -= red[1+i]*inv;
        #pragma unroll
        for (int pp = 0; pp < NP; pp++) au[j][pp] -= red[9+pp]*inv;
        ctd[j] = qd[0]*at[j][0] + qd[1]*at[j][1] + qd[2]*at[j][2] + qd[3]*at[j][3];
    }

    // pass B: c^2, c*cdot_i, (cdot_a*cdot_b + c*cddot_p)
    p[0] = av[0]*av[0] + av[1]*av[1];
    #pragma unroll
    for (int i = 0; i < 8; i++)
        p[1+i] = av[0]*at[0][i] + av[1]*at[1][i];
    #pragma unroll
    for (int pp = 0; pp < NP; pp++){
        double acc = 0.0;
        #pragma unroll
        for (int j = 0; j < NPT; j++){
            double cta = (PA[pp] == 8) ? ctd[j] : at[j][PA[pp]];
            acc += cta*at[j][PB[pp]] + av[j]*au[j][pp];
        }
        p[9+pp] = acc;
    }
    block_reduce_d<NC>(p, red2, wsum, tid);

    double uvar = red2[0]*inv + LN_EPS;
    double r  = 1.0/sqrt(uvar);
    double r3 = r*r*r;
    double r5 = r3*r*r;
    double ud[8], rd[8];
    #pragma unroll
    for (int i = 0; i < 8; i++){ ud[i] = 2.0*red2[1+i]*inv; rd[i] = -0.5*r3*ud[i]; }
    double udd = qd[0]*ud[0] + qd[1]*ud[1] + qd[2]*ud[2] + qd[3]*ud[3];
    double rdd = -0.5*r3*udd;

    // per-pair r'' scalars
    double rpp[NP];
    #pragma unroll
    for (int pp = 0; pp < NP; pp++){
        int a = PA[pp], b_ = PB[pp];
        double uu  = 2.0*red2[9+pp]*inv;
        double uda = (a == 8) ? udd : ud[a];
        rpp[pp] = 0.75*r5*uda*ud[b_] - 0.5*r3*uu;
    }

    #pragma unroll
    for (int j = 0; j < NPT; j++){
        int o = tid + j*NTHREADS;
        double gg = (double)g[o], bb = (double)be[o];
        double c  = av[j];
        #pragma unroll
        for (int pp = 0; pp < NP; pp++){
            int a = PA[pp], b_ = PB[pp];
            double rda = (a == 8) ? rdd    : rd[a];
            double cta = (a == 8) ? ctd[j] : at[j][a];
            au[j][pp] = gg*( au[j][pp]*r + cta*rd[b_] + at[j][b_]*rda + c*rpp[pp] );
        }
        #pragma unroll
        for (int i = 0; i < 8; i++) at[j][i] = gg*(at[j][i]*r + c*rd[i]);
        av[j] = gg*(c*r) + bb;
    }
}

// GEMM layer: double accumulation; weights staged fp32 (exact), promoted at use.
__device__ __forceinline__ void gemm_layer(
    const float* __restrict__ W, const float* __restrict__ b,
    const double* state, float* wtile, int tid,
    double av[NPT], double at[NPT][8], double au[NPT][NP])
{
    double acc[NPT][NC];
    #pragma unroll
    for (int j = 0; j < NPT; j++)
        #pragma unroll
        for (int c = 0; c < NC; c++) acc[j][c] = 0.0;

    for (int kt = 0; kt < HD/KT; kt++){
        __syncthreads();
        #pragma unroll
        for (int it = 0; it < (HD*KT/NTHREADS); it++){
            int idx = tid + it*NTHREADS;
            int o = idx >> 4, kk = idx & 15;
            wtile[o*WPAD + kk] = W[o*HD + kt*KT + kk];
        }
        __syncthreads();
        #pragma unroll 4
        for (int kk = 0; kk < KT; kk++){
            int k = kt*KT + kk;
            const double* sp = state + k*CP;
            double w0 = (double)wtile[(tid)*WPAD + kk];
            double w1 = (double)wtile[(tid + NTHREADS)*WPAD + kk];
            #pragma unroll
            for (int c = 0; c < NC; c++){
                double s = sp[c];                 // warp-uniform -> LDS broadcast
                acc[0][c] += w0*s;
                acc[1][c] += w1*s;
            }
        }
    }
    #pragma unroll
    for (int j = 0; j < NPT; j++){
        int o = tid + j*NTHREADS;
        av[j] = acc[j][0] + (double)b[o];
        #pragma unroll
        for (int i = 0; i < 8; i++)  at[j][i]  = acc[j][1+i];
        #pragma unroll
        for (int pp = 0; pp < NP; pp++) au[j][pp] = acc[j][9+pp];
    }
}

__device__ __forceinline__ void write_state(
    double* state, int tid, const double av[NPT], const double at[NPT][8], const double au[NPT][NP])
{
    #pragma unroll
    for (int j = 0; j < NPT; j++){
        int o = tid + j*NTHREADS;
        double* st = state + o*CP;
        st[0] = av[j];
        #pragma unroll
        for (int i = 0; i < 8; i++)  st[1+i] = at[j][i];
        #pragma unroll
        for (int pp = 0; pp < NP; pp++) st[9+pp] = au[j][pp];
        st[23] = 0.0;
    }
}

__global__ void __launch_bounds__(NTHREADS, 1)
lnn_kernel(const float* __restrict__ x,
           const float* __restrict__ W0, const float* __restrict__ b0,
           const float* __restrict__ g0, const float* __restrict__ be0,
           const float* __restrict__ W1, const float* __restrict__ b1,
           const float* __restrict__ g1, const float* __restrict__ be1,
           const float* __restrict__ W2, const float* __restrict__ b2,
           const float* __restrict__ g2, const float* __restrict__ be2,
           const float* __restrict__ W3,
           float* __restrict__ out)
{
    extern __shared__ double dsmem[];
    double* wsum  = dsmem;                        // 8*CP doubles
    double* red   = wsum + (NTHREADS/32)*CP;      // CP
    double* red2  = red + CP;                     // CP
    double* state = red2 + CP;                    // HD*CP doubles
    float*  wtile = (float*)(state + HD*CP);      // HD*WPAD floats

    const int tid = threadIdx.x;
    const int s   = blockIdx.x;

    double q[8];
    #pragma unroll
    for (int i = 0; i < 8; i++) q[i] = (double)x[s*8 + i];
    const double qd[4] = {q[4], q[5], q[6], q[7]};

    double av[NPT], at[NPT][8], au[NPT][NP];

    // ---- layer 0: z = W0 q + b0; tangents are W0 columns (exact fp32); curvature 0 ----
    #pragma unroll
    for (int j = 0; j < NPT; j++){
        int o = tid + j*NTHREADS;
        double z = (double)b0[o];
        #pragma unroll
        for (int i = 0; i < 8; i++){
            double w = (double)W0[o*8 + i];
            z += w*q[i];
            at[j][i] = w;
        }
        av[j] = z;
        #pragma unroll
        for (int pp = 0; pp < NP; pp++) au[j][pp] = 0.0;
        softplus_stage(av[j], at[j], au[j], qd);
    }
    ln_stage(av, at, au, g0, be0, qd, red, red2, wsum, tid);
    write_state(state, tid, av, at, au);

    // ---- layer 1 ----
    gemm_layer(W1, b1, state, wtile, tid, av, at, au);
    #pragma unroll
    for (int j = 0; j < NPT; j++) softplus_stage(av[j], at[j], au[j], qd);
    ln_stage(av, at, au, g1, be1, qd, red, red2, wsum, tid);
    write_state(state, tid, av, at, au);

    // ---- layer 2 ----
    gemm_layer(W2, b2, state, wtile, tid, av, at, au);
    #pragma unroll
    for (int j = 0; j < NPT; j++) softplus_stage(av[j], at[j], au[j], qd);
    ln_stage(av, at, au, g2, be2, qd, red, red2, wsum, tid);

    // ---- final head: J_i = sum W3_o adot_i, H_p = sum W3_o addot_p ----
    {
        double w3[NPT] = { (double)W3[tid], (double)W3[tid + NTHREADS] };
        double pf[18];
        #pragma unroll
        for (int i = 0; i < 4; i++)
            pf[i] = w3[0]*at[0][i] + w3[1]*at[1][i];
        #pragma unroll
        for (int pp = 0; pp < NP; pp++)
            pf[4+pp] = w3[0]*au[0][pp] + w3[1]*au[1][pp];
        block_reduce_d<18>(pf, red, wsum, tid);
    }

    if (tid == 0){
        double Jv[4], Hp[NP];
        #pragma unroll
        for (int k = 0; k < 4; k++) Jv[k] = red[k];
        #pragma unroll
        for (int pp = 0; pp < NP; pp++) Hp[pp] = red[4+pp];
        const int SI[4][4] = {{0,1,2,3},{1,4,5,6},{2,5,7,8},{3,6,8,9}};
        double A[4][4], rhs[4];
        for (int k = 0; k < 4; k++){
            for (int l = 0; l < 4; l++) A[k][l] = Hp[SI[k][l]];
            rhs[k] = Jv[k] - Hp[10+k];
        }
        // LU with partial pivoting
        for (int c = 0; c < 4; c++){
            int piv = c; double mx = fabs(A[c][c]);
            for (int rdx = c+1; rdx < 4; rdx++){
                double a_ = fabs(A[rdx][c]);
                if (a_ > mx){ mx = a_; piv = rdx; }
            }
            if (piv != c){
                for (int l = 0; l < 4; l++){ double t = A[c][l]; A[c][l] = A[piv][l]; A[piv][l] = t; }
                double t = rhs[c]; rhs[c] = rhs[piv]; rhs[piv] = t;
            }
            double d = A[c][c];
            for (int rdx = c+1; rdx < 4; rdx++){
                double f = A[rdx][c]/d;
                for (int l = c; l < 4; l++) A[rdx][l] -= f*A[c][l];
                rhs[rdx] -= f*rhs[c];
            }
        }
        double xx[4];
        for (int k = 3; k >= 0; k--){
            double sum = rhs[k];
            for (int l = k+1; l < 4; l++) sum -= A[k][l]*xx[l];
            xx[k] = sum / A[k][k];
        }
        #pragma unroll
        for (int k = 0; k < 4; k++) out[s*4 + k] = (float)xx[k];
    }
}

extern "C" void kernel_launch(void* const* d_in, const int* in_sizes, int n_in,
                              void* d_out, int out_size)
{
    const float* x   = (const float*)d_in[0];
    const float* W0  = (const float*)d_in[1];
    const float* b0  = (const float*)d_in[2];
    const float* g0  = (const float*)d_in[3];
    const float* be0 = (const float*)d_in[4];
    const float* W1  = (const float*)d_in[5];
    const float* b1  = (const float*)d_in[6];
    const float* g1  = (const float*)d_in[7];
    const float* be1 = (const float*)d_in[8];
    const float* W2  = (const float*)d_in[9];
    const float* b2  = (const float*)d_in[10];
    const float* g2  = (const float*)d_in[11];
    const float* be2 = (const float*)d_in[12];
    const float* W3  = (const float*)d_in[13];
    float* out = (float*)d_out;

    int B = in_sizes[0] / 8;
    size_t shmem = (size_t)((NTHREADS/32)*CP + 2*CP + HD*CP) * sizeof(double)
                 + (size_t)(HD*WPAD) * sizeof(float);
    cudaFuncSetAttribute(lnn_kernel, cudaFuncAttributeMaxDynamicSharedMemorySize, (int)shmem);
    lnn_kernel<<<B, NTHREADS, shmem>>>(x, W0, b0, g0, be0, W1, b1, g1, be1,
                                       W2, b2, g2, be2, W3, out);
}

// round 10
// speedup vs baseline: 8.5842x; 8.5842x over previous
#include <cuda_runtime.h>
#include <math.h>

#define NTHREADS 256
#define HD 512
#define NPT 2          // neurons per thread
#define NC 23          // channels: 1 value + 8 tangents + 14 second-order
#define CP 24          // padded channel stride (floats in state)
#define NV 12          // f32x2 vector channels (24 floats)
#define KT 16          // k-tile for W staging
#define WPAD 17        // padded wtile row (conflict-free LDS, odd stride)
#define NP 14          // second-order pair channels
#define LN_EPS 1e-5

typedef unsigned long long ull;

__device__ __forceinline__ ull pk2(float lo, float hi){
    ull r; asm("mov.b64 %0,{%1,%2};" : "=l"(r) : "f"(lo), "f"(hi)); return r;
}
__device__ __forceinline__ ull ffma2(ull a, ull b, ull c){
    ull d; asm("fma.rn.f32x2 %0,%1,%2,%3;" : "=l"(d) : "l"(a), "l"(b), "l"(c)); return d;
}
__device__ __forceinline__ ull fmul2(ull a, ull b){
    ull d; asm("mul.rn.f32x2 %0,%1,%2;" : "=l"(d) : "l"(a), "l"(b)); return d;
}
__device__ __forceinline__ ull fadd2(ull a, ull b){
    ull d; asm("add.rn.f32x2 %0,%1,%2;" : "=l"(d) : "l"(a), "l"(b)); return d;
}
__device__ __forceinline__ void upk2(ull v, float& lo, float& hi){
    asm("mov.b64 {%0,%1},%2;" : "=f"(lo), "=f"(hi) : "l"(v));
}

// double-precision block reduction over the CTA (N channels)
template<int N>
__device__ __forceinline__ void block_reduce_d(const double (&p)[N], double* red, double* wsum, int tid){
    int lane = tid & 31, w = tid >> 5;
    #pragma unroll
    for (int q = 0; q < N; q++){
        double v = p[q];
        v += __shfl_down_sync(0xffffffffu, v, 16);
        v += __shfl_down_sync(0xffffffffu, v, 8);
        v += __shfl_down_sync(0xffffffffu, v, 4);
        v += __shfl_down_sync(0xffffffffu, v, 2);
        v += __shfl_down_sync(0xffffffffu, v, 1);
        if (lane == 0) wsum[w*CP + q] = v;
    }
    __syncthreads();
    if (tid < N){
        double s = 0.0;
        #pragma unroll
        for (int w2 = 0; w2 < NTHREADS/32; w2++) s += wsum[w2*CP + tid];
        red[tid] = s;
    }
    __syncthreads();
}

// softplus jet, full double (unchanged from passing R8 kernel)
__device__ __forceinline__ void softplus_stage(double& v, double t[8], double u[NP], const double qd[4]){
    const int PA[NP] = {4,4,4,4,5,5,5,6,6,7, 8,8,8,8};
    const int PB[NP] = {4,5,6,7,5,6,7,6,7,7, 4,5,6,7};
    double z   = v;
    double ezn = exp(-fabs(z));
    double sg  = (z >= 0.0) ? 1.0/(1.0 + ezn) : ezn/(1.0 + ezn);
    double sp  = fmax(z, 0.0) + log1p(ezn);
    double spp = sg*(1.0 - sg);
    double td  = qd[0]*t[0] + qd[1]*t[1] + qd[2]*t[2] + qd[3]*t[3];
    #pragma unroll
    for (int pp = 0; pp < NP; pp++){
        double ta = (PA[pp] == 8) ? td : t[PA[pp]];
        u[pp] = spp*ta*t[PB[pp]] + sg*u[pp];
    }
    #pragma unroll
    for (int i = 0; i < 8; i++) t[i] = sg*t[i];
    v = sp;
}

// LayerNorm jet (unchanged from passing R8 kernel — full double)
__device__ __forceinline__ void ln_stage(
    double av[NPT], double at[NPT][8], double au[NPT][NP],
    const float* __restrict__ g, const float* __restrict__ be,
    const double qd[4], double* red, double* red2, double* wsum, int tid)
{
    const int PA[NP] = {4,4,4,4,5,5,5,6,6,7, 8,8,8,8};
    const int PB[NP] = {4,5,6,7,5,6,7,6,7,7, 4,5,6,7};
    const double inv = 1.0/(double)HD;

    double p[NC];
    p[0] = av[0] + av[1];
    #pragma unroll
    for (int i = 0; i < 8; i++)  p[1+i] = at[0][i] + at[1][i];
    #pragma unroll
    for (int pp = 0; pp < NP; pp++) p[9+pp] = au[0][pp] + au[1][pp];
    block_reduce_d<NC>(p, red, wsum, tid);

    double ctd[NPT];
    double m = red[0]*inv;
    #pragma unroll
    for (int j = 0; j < NPT; j++){
        av[j] -= m;
        #pragma unroll
        for (int i = 0; i < 8; i++)  at[j][i] -= red[1+i]*inv;
        #pragma unroll
        for (int pp = 0; pp < NP; pp++) au[j][pp] -= red[9+pp]*inv;
        ctd[j] = qd[0]*at[j][0] + qd[1]*at[j][1] + qd[2]*at[j][2] + qd[3]*at[j][3];
    }

    p[0] = av[0]*av[0] + av[1]*av[1];
    #pragma unroll
    for (int i = 0; i < 8; i++)
        p[1+i] = av[0]*at[0][i] + av[1]*at[1][i];
    #pragma unroll
    for (int pp = 0; pp < NP; pp++){
        double acc = 0.0;
        #pragma unroll
        for (int j = 0; j < NPT; j++){
            double cta = (PA[pp] == 8) ? ctd[j] : at[j][PA[pp]];
            acc += cta*at[j][PB[pp]] + av[j]*au[j][pp];
        }
        p[9+pp] = acc;
    }
    block_reduce_d<NC>(p, red2, wsum, tid);

    double uvar = red2[0]*inv + LN_EPS;
    double r  = 1.0/sqrt(uvar);
    double r3 = r*r*r;
    double r5 = r3*r*r;
    double ud[8], rd[8];
    #pragma unroll
    for (int i = 0; i < 8; i++){ ud[i] = 2.0*red2[1+i]*inv; rd[i] = -0.5*r3*ud[i]; }
    double udd = qd[0]*ud[0] + qd[1]*ud[1] + qd[2]*ud[2] + qd[3]*ud[3];
    double rdd = -0.5*r3*udd;

    double rpp[NP];
    #pragma unroll
    for (int pp = 0; pp < NP; pp++){
        int a = PA[pp], b_ = PB[pp];
        double uu  = 2.0*red2[9+pp]*inv;
        double uda = (a == 8) ? udd : ud[a];
        rpp[pp] = 0.75*r5*uda*ud[b_] - 0.5*r3*uu;
    }

    #pragma unroll
    for (int j = 0; j < NPT; j++){
        int o = tid + j*NTHREADS;
        double gg = (double)g[o], bb = (double)be[o];
        double c  = av[j];
        #pragma unroll
        for (int pp = 0; pp < NP; pp++){
            int a = PA[pp], b_ = PB[pp];
            double rda = (a == 8) ? rdd    : rd[a];
            double cta = (a == 8) ? ctd[j] : at[j][a];
            au[j][pp] = gg*( au[j][pp]*r + cta*rd[b_] + at[j][b_]*rda + c*rpp[pp] );
        }
        #pragma unroll
        for (int i = 0; i < 8; i++) at[j][i] = gg*(at[j][i]*r + c*rd[i]);
        av[j] = gg*(c*r) + bb;
    }
}

// GEMM layer on the fp32 f32x2 pipe with hierarchical compensated accumulation:
// chunk of 8 k plain FFMA2 into A, Fast2Sum merge of A into (M, C) every 8 k.
// Per-entry noise ~2.6e-7 (≈8-10x better than naive fp32), zero fp64 in the loop.
__device__ __forceinline__ void gemm_layer(
    const float* __restrict__ W, const float* __restrict__ b,
    const float* state, float* wtile, int tid,
    double av[NPT], double at[NPT][8], double au[NPT][NP])
{
    ull M[NPT][NV], C[NPT][NV];
    const ull Z = 0ull;
    #pragma unroll
    for (int j = 0; j < NPT; j++)
        #pragma unroll
        for (int c = 0; c < NV; c++){ M[j][c] = Z; C[j][c] = Z; }
    const ull NEG1 = pk2(-1.0f, -1.0f);

    for (int kt = 0; kt < HD/KT; kt++){
        __syncthreads();
        // stage W tile: float4 LDG, scalar STS into WPAD=17 layout
        #pragma unroll
        for (int it = 0; it < (HD*KT/4/NTHREADS); it++){
            int idx = tid + it*NTHREADS;           // float4 index
            int o = idx >> 2, qq = idx & 3;
            float4 wv = *reinterpret_cast<const float4*>(W + o*HD + kt*KT + qq*4);
            float* dst = wtile + o*WPAD + qq*4;
            dst[0] = wv.x; dst[1] = wv.y; dst[2] = wv.z; dst[3] = wv.w;
        }
        __syncthreads();

        #pragma unroll
        for (int ch = 0; ch < KT/8; ch++){
            ull A[NPT][NV];
            #pragma unroll
            for (int kk8 = 0; kk8 < 8; kk8++){
                int kk = ch*8 + kk8;
                int k  = kt*KT + kk;
                const ulonglong2* sp = reinterpret_cast<const ulonglong2*>(state + k*CP);
                ull sv[NV];
                #pragma unroll
                for (int mm = 0; mm < NV/2; mm++){
                    ulonglong2 t2 = sp[mm];
                    sv[2*mm] = t2.x; sv[2*mm+1] = t2.y;
                }
                float w0 = wtile[(tid)*WPAD + kk];
                float w1 = wtile[(tid + NTHREADS)*WPAD + kk];
                ull w20 = pk2(w0, w0), w21 = pk2(w1, w1);
                if (kk8 == 0){
                    #pragma unroll
                    for (int c = 0; c < NV; c++){
                        A[0][c] = fmul2(w20, sv[c]);
                        A[1][c] = fmul2(w21, sv[c]);
                    }
                } else {
                    #pragma unroll
                    for (int c = 0; c < NV; c++){
                        A[0][c] = ffma2(w20, sv[c], A[0][c]);
                        A[1][c] = ffma2(w21, sv[c], A[1][c]);
                    }
                }
            }
            // Fast2Sum merge: (M, C) += A  (exact-ish compensated add on fp32 pipe)
            #pragma unroll
            for (int j = 0; j < NPT; j++)
                #pragma unroll
                for (int c = 0; c < NV; c++){
                    ull t = fadd2(M[j][c], A[j][c]);
                    ull d = ffma2(t, NEG1, M[j][c]);   // M - t (exact)
                    ull e = fadd2(d, A[j][c]);         // lost low bits
                    C[j][c] = fadd2(C[j][c], e);
                    M[j][c] = t;
                }
        }
    }
    // reconstruct in double: value = M + C
    #pragma unroll
    for (int j = 0; j < NPT; j++){
        int o = tid + j*NTHREADS;
        double chd[24];
        #pragma unroll
        for (int c = 0; c < NV; c++){
            float m0, m1, c0, c1;
            upk2(M[j][c], m0, m1);
            upk2(C[j][c], c0, c1);
            chd[2*c]   = (double)m0 + (double)c0;
            chd[2*c+1] = (double)m1 + (double)c1;
        }
        av[j] = chd[0] + (double)b[o];
        #pragma unroll
        for (int i = 0; i < 8; i++)  at[j][i]  = chd[1+i];
        #pragma unroll
        for (int pp = 0; pp < NP; pp++) au[j][pp] = chd[9+pp];
    }
}

__device__ __forceinline__ void write_state(
    float* state, int tid, const double av[NPT], const double at[NPT][8], const double au[NPT][NP])
{
    #pragma unroll
    for (int j = 0; j < NPT; j++){
        int o = tid + j*NTHREADS;
        float* st = state + o*CP;
        st[0] = (float)av[j];
        #pragma unroll
        for (int i = 0; i < 8; i++)  st[1+i] = (float)at[j][i];
        #pragma unroll
        for (int pp = 0; pp < NP; pp++) st[9+pp] = (float)au[j][pp];
        st[23] = 0.f;
    }
}

__global__ void __launch_bounds__(NTHREADS)
lnn_kernel(const float* __restrict__ x,
           const float* __restrict__ W0, const float* __restrict__ b0,
           const float* __restrict__ g0, const float* __restrict__ be0,
           const float* __restrict__ W1, const float* __restrict__ b1,
           const float* __restrict__ g1, const float* __restrict__ be1,
           const float* __restrict__ W2, const float* __restrict__ b2,
           const float* __restrict__ g2, const float* __restrict__ be2,
           const float* __restrict__ W3,
           float* __restrict__ out)
{
    extern __shared__ double dsmem[];
    double* wsum  = dsmem;                        // 8*CP doubles
    double* red   = wsum + (NTHREADS/32)*CP;      // CP
    double* red2  = red + CP;                     // CP
    float*  state = (float*)(red2 + CP);          // HD*CP floats (16B aligned: 240 doubles)
    float*  wtile = state + HD*CP;                // HD*WPAD floats

    const int tid = threadIdx.x;
    const int s   = blockIdx.x;

    double q[8];
    #pragma unroll
    for (int i = 0; i < 8; i++) q[i] = (double)x[s*8 + i];
    const double qd[4] = {q[4], q[5], q[6], q[7]};

    double av[NPT], at[NPT][8], au[NPT][NP];

    // ---- layer 0: z = W0 q + b0; tangents are W0 columns (exact fp32); curvature 0 ----
    #pragma unroll
    for (int j = 0; j < NPT; j++){
        int o = tid + j*NTHREADS;
        double z = (double)b0[o];
        #pragma unroll
        for (int i = 0; i < 8; i++){
            double w = (double)W0[o*8 + i];
            z += w*q[i];
            at[j][i] = w;
        }
        av[j] = z;
        #pragma unroll
        for (int pp = 0; pp < NP; pp++) au[j][pp] = 0.0;
        softplus_stage(av[j], at[j], au[j], qd);
    }
    ln_stage(av, at, au, g0, be0, qd, red, red2, wsum, tid);
    write_state(state, tid, av, at, au);

    // ---- layer 1 ----
    gemm_layer(W1, b1, state, wtile, tid, av, at, au);
    #pragma unroll
    for (int j = 0; j < NPT; j++) softplus_stage(av[j], at[j], au[j], qd);
    ln_stage(av, at, au, g1, be1, qd, red, red2, wsum, tid);
    __syncthreads();               // state readers done (gemm ended with sync? ensure before overwrite)
    write_state(state, tid, av, at, au);

    // ---- layer 2 ----
    gemm_layer(W2, b2, state, wtile, tid, av, at, au);
    #pragma unroll
    for (int j = 0; j < NPT; j++) softplus_stage(av[j], at[j], au[j], qd);
    ln_stage(av, at, au, g2, be2, qd, red, red2, wsum, tid);

    // ---- final head: J_i = sum W3_o adot_i, H_p = sum W3_o addot_p (double) ----
    {
        double w3[NPT] = { (double)W3[tid], (double)W3[tid + NTHREADS] };
        double pf[18];
        #pragma unroll
        for (int i = 0; i < 4; i++)
            pf[i] = w3[0]*at[0][i] + w3[1]*at[1][i];
        #pragma unroll
        for (int pp = 0; pp < NP; pp++)
            pf[4+pp] = w3[0]*au[0][pp] + w3[1]*au[1][pp];
        block_reduce_d<18>(pf, red, wsum, tid);
    }

    if (tid == 0){
        double Jv[4], Hp[NP];
        #pragma unroll
        for (int k = 0; k < 4; k++) Jv[k] = red[k];
        #pragma unroll
        for (int pp = 0; pp < NP; pp++) Hp[pp] = red[4+pp];
        const int SI[4][4] = {{0,1,2,3},{1,4,5,6},{2,5,7,8},{3,6,8,9}};
        double A[4][4], rhs[4];
        for (int k = 0; k < 4; k++){
            for (int l = 0; l < 4; l++) A[k][l] = Hp[SI[k][l]];
            rhs[k] = Jv[k] - Hp[10+k];
        }
        for (int c = 0; c < 4; c++){
            int piv = c; double mx = fabs(A[c][c]);
            for (int rdx = c+1; rdx < 4; rdx++){
                double a_ = fabs(A[rdx][c]);
                if (a_ > mx){ mx = a_; piv = rdx; }
            }
            if (piv != c){
                for (int l = 0; l < 4; l++){ double t = A[c][l]; A[c][l] = A[piv][l]; A[piv][l] = t; }
                double t = rhs[c]; rhs[c] = rhs[piv]; rhs[piv] = t;
            }
            double d = A[c][c];
            for (int rdx = c+1; rdx < 4; rdx++){
                double f = A[rdx][c]/d;
                for (int l = c; l < 4; l++) A[rdx][l] -= f*A[c][l];
                rhs[rdx] -= f*rhs[c];
            }
        }
        double xx[4];
        for (int k = 3; k >= 0; k--){
            double sum = rhs[k];
            for (int l = k+1; l < 4; l++) sum -= A[k][l]*xx[l];
            xx[k] = sum / A[k][k];
        }
        #pragma unroll
        for (int k = 0; k < 4; k++) out[s*4 + k] = (float)xx[k];
    }
}

extern "C" void kernel_launch(void* const* d_in, const int* in_sizes, int n_in,
                              void* d_out, int out_size)
{
    const float* x   = (const float*)d_in[0];
    const float* W0  = (const float*)d_in[1];
    const float* b0  = (const float*)d_in[2];
    const float* g0  = (const float*)d_in[3];
    const float* be0 = (const float*)d_in[4];
    const float* W1  = (const float*)d_in[5];
    const float* b1  = (const float*)d_in[6];
    const float* g1  = (const float*)d_in[7];
    const float* be1 = (const float*)d_in[8];
    const float* W2  = (const float*)d_in[9];
    const float* b2  = (const float*)d_in[10];
    const float* g2  = (const float*)d_in[11];
    const float* be2 = (const float*)d_in[12];
    const float* W3  = (const float*)d_in[13];
    float* out = (float*)d_out;

    int B = in_sizes[0] / 8;
    size_t shmem = (size_t)((NTHREADS/32)*CP + 2*CP) * sizeof(double)
                 + (size_t)(HD*CP + HD*WPAD) * sizeof(float);
    cudaFuncSetAttribute(lnn_kernel, cudaFuncAttributeMaxDynamicSharedMemorySize, (int)shmem);
    lnn_kernel<<<B, NTHREADS, shmem>>>(x, W0, b0, g0, be0, W1, b1, g1, be1,
                                       W2, b2, g2, be2, W3, out);
}

// round 13
// speedup vs baseline: 10.7962x; 1.2577x over previous
#include <cuda_runtime.h>
#include <math.h>

#define NTHREADS 256
#define HD 512
#define NPT 2          // neurons per thread
#define NC 23          // live channels
#define CP 24          // padded channel stride (floats in state)
#define NV 12          // packed f32x2 channel pairs
#define KT 16          // k-tile for W staging
#define WPAD 17        // padded wtile row (conflict-free)
#define NP 14          // second-order pair channels
#define NWARP (NTHREADS/32)

typedef unsigned long long ull;

// ---------------- packed f32x2 primitives (GEMM + reductions) ----------------
__device__ __forceinline__ ull pk2(float lo, float hi){
    ull r; asm("mov.b64 %0,{%1,%2};" : "=l"(r) : "f"(lo), "f"(hi)); return r;
}
__device__ __forceinline__ ull ffma2(ull a, ull b, ull c){
    ull d; asm("fma.rn.f32x2 %0,%1,%2,%3;" : "=l"(d) : "l"(a), "l"(b), "l"(c)); return d;
}
__device__ __forceinline__ ull fmul2(ull a, ull b){
    ull d; asm("mul.rn.f32x2 %0,%1,%2;" : "=l"(d) : "l"(a), "l"(b)); return d;
}
__device__ __forceinline__ ull fadd2(ull a, ull b){
    ull d; asm("add.rn.f32x2 %0,%1,%2;" : "=l"(d) : "l"(a), "l"(b)); return d;
}
__device__ __forceinline__ void upk2(ull v, float& lo, float& hi){
    asm("mov.b64 {%0,%1},%2;" : "=f"(lo), "=f"(hi) : "l"(v));
}

// ---------------- scalar double-float (df32) primitives ----------------
struct df { float h, l; };
__device__ __forceinline__ df mkdf(float h, float l){ df r; r.h = h; r.l = l; return r; }
__device__ __forceinline__ df renorm(float h, float l){
    float s = h + l;
    float e = (h - s) + l;          // Fast2Sum (|h| >= |l| in all our uses)
    return mkdf(s, e);
}
__device__ __forceinline__ df df_from_d(double d){
    float h = (float)d;
    float l = (float)(d - (double)h);   // exact split
    return mkdf(h, l);
}
__device__ __forceinline__ double d_from(df a){ return (double)a.h + (double)a.l; }
__device__ __forceinline__ df df_add(df a, df b){
    float s  = a.h + b.h;
    float bb = s - a.h;
    float e  = (a.h - (s - bb)) + (b.h - bb);   // TwoSum error (exact)
    e += a.l + b.l;
    return renorm(s, e);
}
__device__ __forceinline__ df df_add_f(df a, float b){
    float s  = a.h + b;
    float bb = s - a.h;
    float e  = (a.h - (s - bb)) + (b - bb);
    e += a.l;
    return renorm(s, e);
}
__device__ __forceinline__ df df_mul(df a, df b){
    float p = a.h * b.h;
    float e = fmaf(a.h, b.h, -p);    // TwoProd error (exact)
    e = fmaf(a.h, b.l, e);
    e = fmaf(a.l, b.h, e);
    return renorm(p, e);
}
__device__ __forceinline__ df df_mul_f(df a, float b){
    float p = a.h * b;
    float e = fmaf(a.h, b, -p);
    e = fmaf(a.l, b, e);
    return renorm(p, e);
}

// ---------------- packed compensated block reduction (as R11, unchanged) ----------------
__device__ __forceinline__ void twosum2(ull& s, ull& e, ull s2, ull e2, ull NEG1){
    ull t  = fadd2(s, s2);
    ull bp = ffma2(s, NEG1, t);
    ull d1 = ffma2(bp, NEG1, t);
    ull r1 = ffma2(d1, NEG1, s);
    ull r2 = ffma2(bp, NEG1, s2);
    e = fadd2(fadd2(e, e2), fadd2(r1, r2));
    s = t;
}

template<int NU>
__device__ __forceinline__ void block_reduce_p(ull (&ps)[NU], ull (&pe)[NU],
                                               double* red, ull* ws, ull* we, int tid){
    int lane = tid & 31, w = tid >> 5;
    const ull NEG1 = pk2(-1.0f, -1.0f);
    #pragma unroll
    for (int q = 0; q < NU; q++){
        ull s = ps[q], e = pe[q];
        #pragma unroll
        for (int off = 16; off; off >>= 1){
            ull s2 = __shfl_down_sync(0xffffffffu, s, off);
            ull e2 = __shfl_down_sync(0xffffffffu, e, off);
            twosum2(s, e, s2, e2, NEG1);
        }
        if (lane == 0){ ws[w*NV + q] = s; we[w*NV + q] = e; }
    }
    __syncthreads();
    if (tid < NU){
        double lo = 0.0, hi = 0.0;
        #pragma unroll
        for (int w2 = 0; w2 < NWARP; w2++){
            float a, b, c, d;
            upk2(ws[w2*NV + tid], a, b);
            upk2(we[w2*NV + tid], c, d);
            lo += (double)a + (double)c;
            hi += (double)b + (double)d;
        }
        red[2*tid] = lo; red[2*tid+1] = hi;
    }
    __syncthreads();
}

// ---------------- softplus jet (df32 vectors; fp64 transcendentals as R10) ----------------
__device__ __forceinline__ void softplus_stage(df& v, df t[8], df u[NP], const float qf[4]){
    const int PA[NP] = {4,4,4,4,5,5,5,6,6,7, 8,8,8,8};   // 8 == direction d
    const int PB[NP] = {4,5,6,7,5,6,7,6,7,7, 4,5,6,7};
    double z    = d_from(v);
    double ezn  = exp(-fabs(z));                         // fp64 libm: fast-math-immune
    double sgd  = (z >= 0.0) ? 1.0/(1.0 + ezn) : ezn/(1.0 + ezn);
    double spd  = fmax(z, 0.0) + log1p(ezn);
    double sppd = sgd*(1.0 - sgd);
    df sg  = df_from_d(sgd);
    df spp = df_from_d(sppd);
    df td = df_mul_f(t[0], qf[0]);
    td = df_add(td, df_mul_f(t[1], qf[1]));
    td = df_add(td, df_mul_f(t[2], qf[2]));
    td = df_add(td, df_mul_f(t[3], qf[3]));
    #pragma unroll
    for (int pp = 0; pp < NP; pp++){
        df ta = (PA[pp] == 8) ? td : t[PA[pp]];
        u[pp] = df_add(df_mul(spp, df_mul(ta, t[PB[pp]])), df_mul(sg, u[pp]));
    }
    #pragma unroll
    for (int i = 0; i < 8; i++) t[i] = df_mul(sg, t[i]);
    v = df_from_d(spd);
}

// ---------------- LayerNorm jet (df32 vectors; fp64 scalar section as R10) ----------------
__device__ __forceinline__ void ln_stage(
    df av[NPT], df at[NPT][8], df au[NPT][NP],
    const float* __restrict__ g, const float* __restrict__ be,
    const float qf[4], const double qdd[4],
    double* red, double* red2, ull* ws, ull* we, int tid)
{
    const int PA[NP] = {4,4,4,4,5,5,5,6,6,7, 8,8,8,8};
    const int PB[NP] = {4,5,6,7,5,6,7,6,7,7, 4,5,6,7};
    const double invd = 1.0/(double)HD;

    // pass A: channel sums (df partials across this thread's 2 neurons)
    ull ps[NV], pe[NV];
    {
        df p[24];
        #pragma unroll
        for (int c = 0; c < 24; c++) p[c] = mkdf(0.f, 0.f);
        #pragma unroll
        for (int j = 0; j < NPT; j++){
            p[0] = df_add(p[0], av[j]);
            #pragma unroll
            for (int i = 0; i < 8; i++)  p[1+i] = df_add(p[1+i], at[j][i]);
            #pragma unroll
            for (int pp = 0; pp < NP; pp++) p[9+pp] = df_add(p[9+pp], au[j][pp]);
        }
        #pragma unroll
        for (int m = 0; m < NV; m++){
            ps[m] = pk2(p[2*m].h, p[2*m+1].h);
            pe[m] = pk2(p[2*m].l, p[2*m+1].l);
        }
    }
    block_reduce_p<NV>(ps, pe, red, ws, we, tid);

    // center: means in fp64 -> df; subtract in df
    df negm[NC];
    #pragma unroll
    for (int c = 0; c < NC; c++) negm[c] = df_from_d(-red[c]*invd);
    df ctd[NPT];
    #pragma unroll
    for (int j = 0; j < NPT; j++){
        av[j] = df_add(av[j], negm[0]);
        #pragma unroll
        for (int i = 0; i < 8; i++)  at[j][i] = df_add(at[j][i], negm[1+i]);
        #pragma unroll
        for (int pp = 0; pp < NP; pp++) au[j][pp] = df_add(au[j][pp], negm[9+pp]);
        df td = df_mul_f(at[j][0], qf[0]);
        td = df_add(td, df_mul_f(at[j][1], qf[1]));
        td = df_add(td, df_mul_f(at[j][2], qf[2]));
        td = df_add(td, df_mul_f(at[j][3], qf[3]));
        ctd[j] = td;
    }

    // pass B: c^2, c*cdot_i, (cdot_a*cdot_b + c*cddot_p) in df
    {
        df p[24];
        #pragma unroll
        for (int c = 0; c < 24; c++) p[c] = mkdf(0.f, 0.f);
        #pragma unroll
        for (int j = 0; j < NPT; j++){
            p[0] = df_add(p[0], df_mul(av[j], av[j]));
            #pragma unroll
            for (int i = 0; i < 8; i++)
                p[1+i] = df_add(p[1+i], df_mul(av[j], at[j][i]));
            #pragma unroll
            for (int pp = 0; pp < NP; pp++){
                df cta = (PA[pp] == 8) ? ctd[j] : at[j][PA[pp]];
                df tm  = df_add(df_mul(cta, at[j][PB[pp]]), df_mul(av[j], au[j][pp]));
                p[9+pp] = df_add(p[9+pp], tm);
            }
        }
        #pragma unroll
        for (int m = 0; m < NV; m++){
            ps[m] = pk2(p[2*m].h, p[2*m+1].h);
            pe[m] = pk2(p[2*m].l, p[2*m+1].l);
        }
    }
    block_reduce_p<NV>(ps, pe, red2, ws, we, tid);

    // fp64 scalar section — computed redundantly by ALL threads (R10 pattern,
    // formulas verbatim), outputs split exactly to df (no demotion to fp32).
    df r_df, rd_df[8], rdd_df, rpp_df[NP];
    {
        double uvar = red2[0]*invd + 1e-5;
        double r  = 1.0/sqrt(uvar);
        double r3 = r*r*r;
        double r5 = r3*r*r;
        double ud[8], rd[8];
        #pragma unroll
        for (int i = 0; i < 8; i++){ ud[i] = 2.0*red2[1+i]*invd; rd[i] = -0.5*r3*ud[i]; }
        double udd = qdd[0]*ud[0] + qdd[1]*ud[1] + qdd[2]*ud[2] + qdd[3]*ud[3];
        double rdd = -0.5*r3*udd;
        r_df = df_from_d(r);
        rdd_df = df_from_d(rdd);
        #pragma unroll
        for (int i = 0; i < 8; i++) rd_df[i] = df_from_d(rd[i]);
        #pragma unroll
        for (int pp = 0; pp < NP; pp++){
            double uu  = 2.0*red2[9+pp]*invd;
            double uda = (PA[pp] == 8) ? udd : ud[PA[pp]];
            rpp_df[pp] = df_from_d(0.75*r5*uda*ud[PB[pp]] - 0.5*r3*uu);
        }
    }

    // apply (df): au first (uses centered at), then at, then av
    #pragma unroll
    for (int j = 0; j < NPT; j++){
        int o = tid + j*NTHREADS;
        float gg = g[o], bb = be[o];
        df c = av[j];
        #pragma unroll
        for (int pp = 0; pp < NP; pp++){
            df rda = (PA[pp] == 8) ? rdd_df : rd_df[PA[pp]];
            df cta = (PA[pp] == 8) ? ctd[j] : at[j][PA[pp]];
            df s1 = df_add(df_mul(au[j][pp], r_df), df_mul(cta, rd_df[PB[pp]]));
            df s2 = df_add(df_mul(at[j][PB[pp]], rda), df_mul(c, rpp_df[pp]));
            au[j][pp] = df_mul_f(df_add(s1, s2), gg);
        }
        #pragma unroll
        for (int i = 0; i < 8; i++)
            at[j][i] = df_mul_f(df_add(df_mul(at[j][i], r_df), df_mul(c, rd_df[i])), gg);
        av[j] = df_add_f(df_mul_f(df_mul(c, r_df), gg), bb);
    }
}

// ---------------- GEMM: byte-identical numerics to passing R10 ----------------
__device__ __forceinline__ void gemm_layer(
    const float* __restrict__ W, const float* __restrict__ b,
    const float* state, float* wtile, int tid,
    df av[NPT], df at[NPT][8], df au[NPT][NP])
{
    ull M[NPT][NV], C[NPT][NV];
    #pragma unroll
    for (int j = 0; j < NPT; j++)
        #pragma unroll
        for (int c = 0; c < NV; c++){ M[j][c] = 0ull; C[j][c] = 0ull; }
    const ull NEG1 = pk2(-1.0f, -1.0f);

    for (int kt = 0; kt < HD/KT; kt++){
        __syncthreads();
        #pragma unroll
        for (int it = 0; it < (HD*KT/NTHREADS); it++){
            int idx = tid + it*NTHREADS;
            int o = idx >> 4, kk = idx & 15;
            wtile[o*WPAD + kk] = W[o*HD + kt*KT + kk];
        }
        __syncthreads();
        #pragma unroll
        for (int ch = 0; ch < KT/8; ch++){
            ull A[NPT][NV];
            #pragma unroll
            for (int kk8 = 0; kk8 < 8; kk8++){
                int kk = ch*8 + kk8;
                int k  = kt*KT + kk;
                const ulonglong2* sp = reinterpret_cast<const ulonglong2*>(state + k*CP);
                ull sv[NV];
                #pragma unroll
                for (int mm = 0; mm < NV/2; mm++){
                    ulonglong2 t2 = sp[mm];
                    sv[2*mm] = t2.x; sv[2*mm+1] = t2.y;
                }
                #pragma unroll
                for (int j = 0; j < NPT; j++){
                    float w = wtile[(tid + j*NTHREADS)*WPAD + kk];
                    ull w2 = pk2(w, w);
                    if (kk8 == 0){
                        #pragma unroll
                        for (int c = 0; c < NV; c++) A[j][c] = fmul2(w2, sv[c]);
                    } else {
                        #pragma unroll
                        for (int c = 0; c < NV; c++) A[j][c] = ffma2(w2, sv[c], A[j][c]);
                    }
                }
            }
            #pragma unroll
            for (int j = 0; j < NPT; j++)
                #pragma unroll
                for (int c = 0; c < NV; c++){
                    ull t = fadd2(M[j][c], A[j][c]);
                    ull d = ffma2(t, NEG1, M[j][c]);
                    ull e = fadd2(d, A[j][c]);
                    C[j][c] = fadd2(C[j][c], e);
                    M[j][c] = t;
                }
        }
    }
    // fold (M,C) -> df channels (no fp64)
    #pragma unroll
    for (int j = 0; j < NPT; j++){
        int o = tid + j*NTHREADS;
        df ch[24];
        #pragma unroll
        for (int c = 0; c < NV; c++){
            float m0, m1, c0, c1;
            upk2(M[j][c], m0, m1);
            upk2(C[j][c], c0, c1);
            ch[2*c]   = renorm(m0, c0);
            ch[2*c+1] = renorm(m1, c1);
        }
        av[j] = df_add_f(ch[0], b[o]);
        #pragma unroll
        for (int i = 0; i < 8; i++)  at[j][i]  = ch[1+i];
        #pragma unroll
        for (int pp = 0; pp < NP; pp++) au[j][pp] = ch[9+pp];
    }
}

__device__ __forceinline__ void write_state(
    float* state, int tid, const df av[NPT], const df at[NPT][8], const df au[NPT][NP])
{
    #pragma unroll
    for (int j = 0; j < NPT; j++){
        int o = tid + j*NTHREADS;
        float* st = state + o*CP;
        st[0] = av[j].h + av[j].l;              // single fp32 rounding
        #pragma unroll
        for (int i = 0; i < 8; i++)  st[1+i] = at[j][i].h + at[j][i].l;
        #pragma unroll
        for (int pp = 0; pp < NP; pp++) st[9+pp] = au[j][pp].h + au[j][pp].l;
        st[23] = 0.f;
    }
}

__global__ void __launch_bounds__(NTHREADS)
lnn_kernel(const float* __restrict__ x,
           const float* __restrict__ W0, const float* __restrict__ b0,
           const float* __restrict__ g0, const float* __restrict__ be0,
           const float* __restrict__ W1, const float* __restrict__ b1,
           const float* __restrict__ g1, const float* __restrict__ be1,
           const float* __restrict__ W2, const float* __restrict__ b2,
           const float* __restrict__ g2, const float* __restrict__ be2,
           const float* __restrict__ W3,
           float* __restrict__ out)
{
    extern __shared__ double dsmem[];
    double* red   = dsmem;                       // 24 doubles
    double* red2  = red + 24;                    // 24 doubles
    ull*    ws    = (ull*)(red2 + 24);           // NWARP*NV
    ull*    we    = ws + NWARP*NV;               // NWARP*NV
    float*  state = (float*)(we + NWARP*NV);     // HD*CP floats (16B aligned)
    float*  wtile = state + HD*CP;               // HD*WPAD floats

    const int tid = threadIdx.x;
    const int s   = blockIdx.x;

    float qf8[8];
    #pragma unroll
    for (int i = 0; i < 8; i++) qf8[i] = x[s*8 + i];
    const float  qf[4]  = {qf8[4], qf8[5], qf8[6], qf8[7]};
    const double qdd[4] = {(double)qf8[4], (double)qf8[5], (double)qf8[6], (double)qf8[7]};

    df av[NPT], at[NPT][8], au[NPT][NP];

    // ---- layer 0: z = W0 q + b0 (fp64, as R10); tangents = W0 rows (exact) ----
    #pragma unroll
    for (int j = 0; j < NPT; j++){
        int o = tid + j*NTHREADS;
        double z = (double)b0[o];
        #pragma unroll
        for (int i = 0; i < 8; i++){
            float w = W0[o*8 + i];
            z += (double)w * (double)qf8[i];
            at[j][i] = mkdf(w, 0.f);
        }
        av[j] = df_from_d(z);
        #pragma unroll
        for (int pp = 0; pp < NP; pp++) au[j][pp] = mkdf(0.f, 0.f);
        softplus_stage(av[j], at[j], au[j], qf);
    }
    ln_stage(av, at, au, g0, be0, qf, qdd, red, red2, ws, we, tid);
    write_state(state, tid, av, at, au);

    // ---- layer 1 ----
    gemm_layer(W1, b1, state, wtile, tid, av, at, au);
    #pragma unroll
    for (int j = 0; j < NPT; j++) softplus_stage(av[j], at[j], au[j], qf);
    ln_stage(av, at, au, g1, be1, qf, qdd, red, red2, ws, we, tid);
    write_state(state, tid, av, at, au);

    // ---- layer 2 ----
    gemm_layer(W2, b2, state, wtile, tid, av, at, au);
    #pragma unroll
    for (int j = 0; j < NPT; j++) softplus_stage(av[j], at[j], au[j], qf);
    ln_stage(av, at, au, g2, be2, qf, qdd, red, red2, ws, we, tid);

    // ---- head: J_i = sum w3*adot_i, H_p = sum w3*addot_p (df products) ----
    {
        float w30 = W3[tid], w31 = W3[tid + NTHREADS];
        df pf[18];
        #pragma unroll
        for (int i = 0; i < 4; i++)
            pf[i] = df_add(df_mul_f(at[0][i], w30), df_mul_f(at[1][i], w31));
        #pragma unroll
        for (int pp = 0; pp < NP; pp++)
            pf[4+pp] = df_add(df_mul_f(au[0][pp], w30), df_mul_f(au[1][pp], w31));
        ull ps[9], pe[9];
        #pragma unroll
        for (int m = 0; m < 9; m++){
            ps[m] = pk2(pf[2*m].h, pf[2*m+1].h);
            pe[m] = pk2(pf[2*m].l, pf[2*m+1].l);
        }
        block_reduce_p<9>(ps, pe, red, ws, we, tid);
    }

    if (tid == 0){
        double Jv[4], Hp[NP];
        #pragma unroll
        for (int k = 0; k < 4; k++) Jv[k] = red[k];
        #pragma unroll
        for (int pp = 0; pp < NP; pp++) Hp[pp] = red[4+pp];
        const int SI[4][4] = {{0,1,2,3},{1,4,5,6},{2,5,7,8},{3,6,8,9}};
        double A[4][4], rhs[4];
        for (int k = 0; k < 4; k++){
            for (int l = 0; l < 4; l++) A[k][l] = Hp[SI[k][l]];
            rhs[k] = Jv[k] - Hp[10+k];
        }
        for (int c = 0; c < 4; c++){
            int piv = c; double mx = fabs(A[c][c]);
            for (int rdx = c+1; rdx < 4; rdx++){
                double a_ = fabs(A[rdx][c]);
                if (a_ > mx){ mx = a_; piv = rdx; }
            }
            if (piv != c){
                for (int l = 0; l < 4; l++){ double t = A[c][l]; A[c][l] = A[piv][l]; A[piv][l] = t; }
                double t = rhs[c]; rhs[c] = rhs[piv]; rhs[piv] = t;
            }
            double d = A[c][c];
            for (int rdx = c+1; rdx < 4; rdx++){
                double f = A[rdx][c]/d;
                for (int l = c; l < 4; l++) A[rdx][l] -= f*A[c][l];
                rhs[rdx] -= f*rhs[c];
            }
        }
        double xx[4];
        for (int k = 3; k >= 0; k--){
            double sum = rhs[k];
            for (int l = k+1; l < 4; l++) sum -= A[k][l]*xx[l];
            xx[k] = sum / A[k][k];
        }
        #pragma unroll
        for (int k = 0; k < 4; k++) out[s*4 + k] = (float)xx[k];
    }
}

extern "C" void kernel_launch(void* const* d_in, const int* in_sizes, int n_in,
                              void* d_out, int out_size)
{
    const float* x   = (const float*)d_in[0];
    const float* W0  = (const float*)d_in[1];
    const float* b0  = (const float*)d_in[2];
    const float* g0  = (const float*)d_in[3];
    const float* be0 = (const float*)d_in[4];
    const float* W1  = (const float*)d_in[5];
    const float* b1  = (const float*)d_in[6];
    const float* g1  = (const float*)d_in[7];
    const float* be1 = (const float*)d_in[8];
    const float* W2  = (const float*)d_in[9];
    const float* b2  = (const float*)d_in[10];
    const float* g2  = (const float*)d_in[11];
    const float* be2 = (const float*)d_in[12];
    const float* W3  = (const float*)d_in[13];
    float* out = (float*)d_out;

    int B = in_sizes[0] / 8;
    size_t shmem = 48*sizeof(double) + (size_t)2*NWARP*NV*sizeof(ull)
                 + (size_t)(HD*CP + HD*WPAD)*sizeof(float);
    cudaFuncSetAttribute(lnn_kernel, cudaFuncAttributeMaxDynamicSharedMemorySize, (int)shmem);
    lnn_kernel<<<B, NTHREADS, shmem>>>(x, W0, b0, g0, be0, W1, b1, g1, be1,
                                       W2, b2, g2, be2, W3, out);
}

// round 15
// speedup vs baseline: 13.1067x; 1.2140x over previous
#include <cuda_runtime.h>
#include <math.h>

#define NTHREADS 512
#define HD 512
#define NC 23          // live channels
#define CP 24          // padded channel stride (floats in state)
#define NV 12          // packed f32x2 channel pairs
#define KT 32          // k-tile for W staging
#define WPAD 33        // padded wtile row (odd stride, conflict-free reads)
#define NP 14          // second-order pair channels
#define NWARP (NTHREADS/32)

typedef unsigned long long ull;

__constant__ int d_PA[NP] = {4,4,4,4,5,5,5,6,6,7, 8,8,8,8};
__constant__ int d_PB[NP] = {4,5,6,7,5,6,7,6,7,7, 4,5,6,7};

// ---------------- packed f32x2 primitives ----------------
__device__ __forceinline__ ull pk2(float lo, float hi){
    ull r; asm("mov.b64 %0,{%1,%2};" : "=l"(r) : "f"(lo), "f"(hi)); return r;
}
__device__ __forceinline__ ull ffma2(ull a, ull b, ull c){
    ull d; asm("fma.rn.f32x2 %0,%1,%2,%3;" : "=l"(d) : "l"(a), "l"(b), "l"(c)); return d;
}
__device__ __forceinline__ ull fmul2(ull a, ull b){
    ull d; asm("mul.rn.f32x2 %0,%1,%2;" : "=l"(d) : "l"(a), "l"(b)); return d;
}
__device__ __forceinline__ ull fadd2(ull a, ull b){
    ull d; asm("add.rn.f32x2 %0,%1,%2;" : "=l"(d) : "l"(a), "l"(b)); return d;
}
__device__ __forceinline__ void upk2(ull v, float& lo, float& hi){
    asm("mov.b64 {%0,%1},%2;" : "=f"(lo), "=f"(hi) : "l"(v));
}

// ---------------- scalar double-float (df32) primitives ----------------
struct df { float h, l; };
__device__ __forceinline__ df mkdf(float h, float l){ df r; r.h = h; r.l = l; return r; }
__device__ __forceinline__ df renorm(float h, float l){
    float s = h + l;
    float e = (h - s) + l;
    return mkdf(s, e);
}
__device__ __forceinline__ df df_from_d(double d){
    float h = (float)d;
    float l = (float)(d - (double)h);
    return mkdf(h, l);
}
__device__ __forceinline__ double d_from(df a){ return (double)a.h + (double)a.l; }
__device__ __forceinline__ df df_add(df a, df b){
    float s  = a.h + b.h;
    float bb = s - a.h;
    float e  = (a.h - (s - bb)) + (b.h - bb);
    e += a.l + b.l;
    return renorm(s, e);
}
__device__ __forceinline__ df df_add_f(df a, float b){
    float s  = a.h + b;
    float bb = s - a.h;
    float e  = (a.h - (s - bb)) + (b - bb);
    e += a.l;
    return renorm(s, e);
}
__device__ __forceinline__ df df_mul(df a, df b){
    float p = a.h * b.h;
    float e = fmaf(a.h, b.h, -p);
    e = fmaf(a.h, b.l, e);
    e = fmaf(a.l, b.h, e);
    return renorm(p, e);
}
__device__ __forceinline__ df df_mul_f(df a, float b){
    float p = a.h * b;
    float e = fmaf(a.h, b, -p);
    e = fmaf(a.l, b, e);
    return renorm(p, e);
}

// ---------------- packed compensated block reduction ----------------
__device__ __forceinline__ void twosum2(ull& s, ull& e, ull s2, ull e2, ull NEG1){
    ull t  = fadd2(s, s2);
    ull bp = ffma2(s, NEG1, t);
    ull d1 = ffma2(bp, NEG1, t);
    ull r1 = ffma2(d1, NEG1, s);
    ull r2 = ffma2(bp, NEG1, s2);
    e = fadd2(fadd2(e, e2), fadd2(r1, r2));
    s = t;
}

template<int NU>
__device__ __forceinline__ void block_reduce_p(ull (&ps)[NU], ull (&pe)[NU],
                                               double* red, ull* ws, ull* we, int tid){
    int lane = tid & 31, w = tid >> 5;
    const ull NEG1 = pk2(-1.0f, -1.0f);
    #pragma unroll
    for (int q = 0; q < NU; q++){
        ull s = ps[q], e = pe[q];
        #pragma unroll
        for (int off = 16; off; off >>= 1){
            ull s2 = __shfl_down_sync(0xffffffffu, s, off);
            ull e2 = __shfl_down_sync(0xffffffffu, e, off);
            twosum2(s, e, s2, e2, NEG1);
        }
        if (lane == 0){ ws[w*NV + q] = s; we[w*NV + q] = e; }
    }
    __syncthreads();
    if (tid < NU){
        double lo = 0.0, hi = 0.0;
        #pragma unroll
        for (int w2 = 0; w2 < NWARP; w2++){
            float a, b, c, d;
            upk2(ws[w2*NV + tid], a, b);
            upk2(we[w2*NV + tid], c, d);
            lo += (double)a + (double)c;
            hi += (double)b + (double)d;
        }
        red[2*tid] = lo; red[2*tid+1] = hi;
    }
    __syncthreads();
}

// ---------------- softplus jet (df32 vectors; fp64 transcendentals) ----------------
__device__ __forceinline__ void softplus_stage(df& v, df t[8], df u[NP], const float qf[4]){
    const int PA[NP] = {4,4,4,4,5,5,5,6,6,7, 8,8,8,8};
    const int PB[NP] = {4,5,6,7,5,6,7,6,7,7, 4,5,6,7};
    double z    = d_from(v);
    double ezn  = exp(-fabs(z));
    double sgd  = (z >= 0.0) ? 1.0/(1.0 + ezn) : ezn/(1.0 + ezn);
    double spd  = fmax(z, 0.0) + log1p(ezn);
    double sppd = sgd*(1.0 - sgd);
    df sg  = df_from_d(sgd);
    df spp = df_from_d(sppd);
    df td = df_mul_f(t[0], qf[0]);
    td = df_add(td, df_mul_f(t[1], qf[1]));
    td = df_add(td, df_mul_f(t[2], qf[2]));
    td = df_add(td, df_mul_f(t[3], qf[3]));
    #pragma unroll
    for (int pp = 0; pp < NP; pp++){
        df ta = (PA[pp] == 8) ? td : t[PA[pp]];
        u[pp] = df_add(df_mul(spp, df_mul(ta, t[PB[pp]])), df_mul(sg, u[pp]));
    }
    #pragma unroll
    for (int i = 0; i < 8; i++) t[i] = df_mul(sg, t[i]);
    v = df_from_d(spd);
}

// ---------------- LayerNorm jet (df32 vectors; fp64 scalars by 24 threads, df broadcast) ----------------
__device__ __forceinline__ void ln_stage(
    df& av, df at[8], df au[NP],
    const float* __restrict__ g, const float* __restrict__ be,
    const float qf[4], const double qdd[4],
    double* red, double* red2, ull* ws, ull* we,
    float* negm_h, float* negm_l, float* scal_h, float* scal_l, int tid)
{
    const int PA[NP] = {4,4,4,4,5,5,5,6,6,7, 8,8,8,8};
    const int PB[NP] = {4,5,6,7,5,6,7,6,7,7, 4,5,6,7};
    const double invd = 1.0/(double)HD;

    // pass A: channel sums (pack df state directly)
    ull ps[NV], pe[NV];
    {
        float h[24], l[24];
        h[0] = av.h; l[0] = av.l;
        #pragma unroll
        for (int i = 0; i < 8; i++){ h[1+i] = at[i].h; l[1+i] = at[i].l; }
        #pragma unroll
        for (int pp = 0; pp < NP; pp++){ h[9+pp] = au[pp].h; l[9+pp] = au[pp].l; }
        h[23] = 0.f; l[23] = 0.f;
        #pragma unroll
        for (int m = 0; m < NV; m++){ ps[m] = pk2(h[2*m], h[2*m+1]); pe[m] = pk2(l[2*m], l[2*m+1]); }
    }
    block_reduce_p<NV>(ps, pe, red, ws, we, tid);

    // means: fp64 by 24 threads, broadcast as df
    if (tid < 24){
        double v = -red[tid]*invd;
        float hh = (float)v;
        negm_h[tid] = hh;
        negm_l[tid] = (float)(v - (double)hh);
    }
    __syncthreads();

    // center in df
    av = df_add(av, mkdf(negm_h[0], negm_l[0]));
    #pragma unroll
    for (int i = 0; i < 8; i++)  at[i] = df_add(at[i], mkdf(negm_h[1+i], negm_l[1+i]));
    #pragma unroll
    for (int pp = 0; pp < NP; pp++) au[pp] = df_add(au[pp], mkdf(negm_h[9+pp], negm_l[9+pp]));
    df ctd = df_mul_f(at[0], qf[0]);
    ctd = df_add(ctd, df_mul_f(at[1], qf[1]));
    ctd = df_add(ctd, df_mul_f(at[2], qf[2]));
    ctd = df_add(ctd, df_mul_f(at[3], qf[3]));

    // pass B: products in df, packed pairwise to limit live regs
    #pragma unroll
    for (int m = 0; m < NV; m++){
        df a0, a1;
        int c0 = 2*m, c1 = 2*m + 1;
        // channel -> product mapping: 0:c^2, 1..8: c*cdot_i, 9..22: pair terms, 23: zero
        #pragma unroll
        for (int t2 = 0; t2 < 2; t2++){
            int c = t2 ? c1 : c0;
            df r;
            if (c == 0)      r = df_mul(av, av);
            else if (c < 9)  r = df_mul(av, at[c-1]);
            else if (c < 23){
                int pp = c - 9;
                df cta = (PA[pp] == 8) ? ctd : at[PA[pp]];
                r = df_add(df_mul(cta, at[PB[pp]]), df_mul(av, au[pp]));
            } else r = mkdf(0.f, 0.f);
            if (t2) a1 = r; else a0 = r;
        }
        ps[m] = pk2(a0.h, a1.h);
        pe[m] = pk2(a0.l, a1.l);
    }
    block_reduce_p<NV>(ps, pe, red2, ws, we, tid);

    // fp64 scalar section by threads 0..23, broadcast as df (h,l)
    // scal[0]=r, scal[1..8]=rd, scal[9]=rdd, scal[10..23]=rpp
    if (tid < 24){
        double uvar = red2[0]*invd + 1e-5;
        double rD = 1.0/sqrt(uvar);
        double r3 = rD*rD*rD;
        double vout;
        if (tid < 14){
            int a = d_PA[tid], b_ = d_PB[tid];
            double r5  = r3*rD*rD;
            double udb = 2.0*red2[1+b_]*invd;
            double uda;
            if (a == 8){
                uda = 0.0;
                #pragma unroll
                for (int j = 0; j < 4; j++) uda += qdd[j]*(2.0*red2[1+j]*invd);
            } else {
                uda = 2.0*red2[1+a]*invd;
            }
            double uu = 2.0*red2[9+tid]*invd;
            vout = 0.75*r5*uda*udb - 0.5*r3*uu;
            float hh = (float)vout;
            scal_h[10+tid] = hh; scal_l[10+tid] = (float)(vout - (double)hh);
        } else if (tid == 14){
            vout = rD;
            float hh = (float)vout;
            scal_h[0] = hh; scal_l[0] = (float)(vout - (double)hh);
        } else if (tid == 15){
            double udd = 0.0;
            #pragma unroll
            for (int j = 0; j < 4; j++) udd += qdd[j]*(2.0*red2[1+j]*invd);
            vout = -0.5*r3*udd;
            float hh = (float)vout;
            scal_h[9] = hh; scal_l[9] = (float)(vout - (double)hh);
        } else {
            int i = tid - 16;
            double udi = 2.0*red2[1+i]*invd;
            vout = -0.5*r3*udi;
            float hh = (float)vout;
            scal_h[1+i] = hh; scal_l[1+i] = (float)(vout - (double)hh);
        }
    }
    __syncthreads();

    df r_df = mkdf(scal_h[0], scal_l[0]);
    df rdd_df = mkdf(scal_h[9], scal_l[9]);
    df rd_df[8];
    #pragma unroll
    for (int i = 0; i < 8; i++) rd_df[i] = mkdf(scal_h[1+i], scal_l[1+i]);

    // apply in df
    float gg = g[tid], bb = be[tid];
    df c = av;
    #pragma unroll
    for (int pp = 0; pp < NP; pp++){
        df rda = (PA[pp] == 8) ? rdd_df : rd_df[PA[pp]];
        df cta = (PA[pp] == 8) ? ctd    : at[PA[pp]];
        df rpp = mkdf(scal_h[10+pp], scal_l[10+pp]);
        df s1 = df_add(df_mul(au[pp], r_df), df_mul(cta, rd_df[PB[pp]]));
        df s2 = df_add(df_mul(at[PB[pp]], rda), df_mul(c, rpp));
        au[pp] = df_mul_f(df_add(s1, s2), gg);
    }
    #pragma unroll
    for (int i = 0; i < 8; i++)
        at[i] = df_mul_f(df_add(df_mul(at[i], r_df), df_mul(c, rd_df[i])), gg);
    av = df_add_f(df_mul_f(df_mul(c, r_df), gg), bb);
    __syncthreads();
}

// ---------------- GEMM: chunk-8 compensated f32x2 (R10/R13 numerics verbatim) ----------------
__device__ __forceinline__ void gemm_layer(
    const float* __restrict__ W, const float* __restrict__ b,
    const float* state, float* wtile, int tid,
    df& av, df at[8], df au[NP])
{
    ull M[NV], C[NV];
    #pragma unroll
    for (int c = 0; c < NV; c++){ M[c] = 0ull; C[c] = 0ull; }
    const ull NEG1 = pk2(-1.0f, -1.0f);

    for (int kt = 0; kt < HD/KT; kt++){
        __syncthreads();
        #pragma unroll
        for (int it = 0; it < (HD*KT/4/NTHREADS); it++){   // 8 iters
            int idx = tid + it*NTHREADS;                   // float4 index
            int o = idx >> 3, qq = idx & 7;
            float4 wv = *reinterpret_cast<const float4*>(W + o*HD + kt*KT + qq*4);
            float* dst = wtile + o*WPAD + qq*4;
            dst[0] = wv.x; dst[1] = wv.y; dst[2] = wv.z; dst[3] = wv.w;
        }
        __syncthreads();

        #pragma unroll
        for (int ch = 0; ch < KT/8; ch++){
            ull A[NV];
            #pragma unroll
            for (int kk8 = 0; kk8 < 8; kk8++){
                int kk = ch*8 + kk8;
                int k  = kt*KT + kk;
                const ulonglong2* sp = reinterpret_cast<const ulonglong2*>(state + k*CP);
                float w0 = wtile[tid*WPAD + kk];
                ull w2 = pk2(w0, w0);
                if (kk8 == 0){
                    #pragma unroll
                    for (int mm = 0; mm < NV/2; mm++){
                        ulonglong2 t2 = sp[mm];
                        A[2*mm]   = fmul2(w2, t2.x);
                        A[2*mm+1] = fmul2(w2, t2.y);
                    }
                } else {
                    #pragma unroll
                    for (int mm = 0; mm < NV/2; mm++){
                        ulonglong2 t2 = sp[mm];
                        A[2*mm]   = ffma2(w2, t2.x, A[2*mm]);
                        A[2*mm+1] = ffma2(w2, t2.y, A[2*mm+1]);
                    }
                }
            }
            #pragma unroll
            for (int c = 0; c < NV; c++){
                ull t = fadd2(M[c], A[c]);
                ull d = ffma2(t, NEG1, M[c]);
                ull e = fadd2(d, A[c]);
                C[c] = fadd2(C[c], e);
                M[c] = t;
            }
        }
    }
    // fold (M,C) -> df channels
    {
        df ch[24];
        #pragma unroll
        for (int c = 0; c < NV; c++){
            float m0, m1, c0, c1;
            upk2(M[c], m0, m1);
            upk2(C[c], c0, c1);
            ch[2*c]   = renorm(m0, c0);
            ch[2*c+1] = renorm(m1, c1);
        }
        av = df_add_f(ch[0], b[tid]);
        #pragma unroll
        for (int i = 0; i < 8; i++)  at[i]  = ch[1+i];
        #pragma unroll
        for (int pp = 0; pp < NP; pp++) au[pp] = ch[9+pp];
    }
}

__device__ __forceinline__ void write_state(
    float* state, int tid, df av, const df at[8], const df au[NP])
{
    float* st = state + tid*CP;
    st[0] = av.h + av.l;
    #pragma unroll
    for (int i = 0; i < 8; i++)  st[1+i] = at[i].h + at[i].l;
    #pragma unroll
    for (int pp = 0; pp < NP; pp++) st[9+pp] = au[pp].h + au[pp].l;
    st[23] = 0.f;
}

__global__ void __launch_bounds__(NTHREADS)
lnn_kernel(const float* __restrict__ x,
           const float* __restrict__ W0, const float* __restrict__ b0,
           const float* __restrict__ g0, const float* __restrict__ be0,
           const float* __restrict__ W1, const float* __restrict__ b1,
           const float* __restrict__ g1, const float* __restrict__ be1,
           const float* __restrict__ W2, const float* __restrict__ b2,
           const float* __restrict__ g2, const float* __restrict__ be2,
           const float* __restrict__ W3,
           float* __restrict__ out)
{
    extern __shared__ double dsmem[];
    double* red    = dsmem;                       // 24 doubles
    double* red2   = red + 24;                    // 24 doubles
    ull*    ws     = (ull*)(red2 + 24);           // NWARP*NV
    ull*    we     = ws + NWARP*NV;               // NWARP*NV
    float*  negm_h = (float*)(we + NWARP*NV);     // 24
    float*  negm_l = negm_h + 24;                 // 24
    float*  scal_h = negm_l + 24;                 // 24
    float*  scal_l = scal_h + 24;                 // 24
    float*  state  = scal_l + 24;                 // HD*CP floats (16B aligned)
    float*  wtile  = state + HD*CP;               // HD*WPAD floats

    const int tid = threadIdx.x;
    const int s   = blockIdx.x;

    float qf8[8];
    #pragma unroll
    for (int i = 0; i < 8; i++) qf8[i] = x[s*8 + i];
    const float  qf[4]  = {qf8[4], qf8[5], qf8[6], qf8[7]};
    const double qdd[4] = {(double)qf8[4], (double)qf8[5], (double)qf8[6], (double)qf8[7]};

    df av, at[8], au[NP];

    // ---- layer 0 ----
    {
        double z = (double)b0[tid];
        #pragma unroll
        for (int i = 0; i < 8; i++){
            float w = W0[tid*8 + i];
            z += (double)w * (double)qf8[i];
            at[i] = mkdf(w, 0.f);
        }
        av = df_from_d(z);
        #pragma unroll
        for (int pp = 0; pp < NP; pp++) au[pp] = mkdf(0.f, 0.f);
        softplus_stage(av, at, au, qf);
    }
    ln_stage(av, at, au, g0, be0, qf, qdd, red, red2, ws, we, negm_h, negm_l, scal_h, scal_l, tid);
    write_state(state, tid, av, at, au);

    // ---- layer 1 ----
    gemm_layer(W1, b1, state, wtile, tid, av, at, au);
    softplus_stage(av, at, au, qf);
    ln_stage(av, at, au, g1, be1, qf, qdd, red, red2, ws, we, negm_h, negm_l, scal_h, scal_l, tid);
    write_state(state, tid, av, at, au);

    // ---- layer 2 ----
    gemm_layer(W2, b2, state, wtile, tid, av, at, au);
    softplus_stage(av, at, au, qf);
    ln_stage(av, at, au, g2, be2, qf, qdd, red, red2, ws, we, negm_h, negm_l, scal_h, scal_l, tid);

    // ---- head ----
    {
        float w3 = W3[tid];
        df pf[18];
        #pragma unroll
        for (int i = 0; i < 4; i++)  pf[i] = df_mul_f(at[i], w3);
        #pragma unroll
        for (int pp = 0; pp < NP; pp++) pf[4+pp] = df_mul_f(au[pp], w3);
        ull ps[9], pe[9];
        #pragma unroll
        for (int m = 0; m < 9; m++){
            ps[m] = pk2(pf[2*m].h, pf[2*m+1].h);
            pe[m] = pk2(pf[2*m].l, pf[2*m+1].l);
        }
        block_reduce_p<9>(ps, pe, red, ws, we, tid);
    }

    if (tid == 0){
        double Jv[4], Hp[NP];
        #pragma unroll
        for (int k = 0; k < 4; k++) Jv[k] = red[k];
        #pragma unroll
        for (int pp = 0; pp < NP; pp++) Hp[pp] = red[4+pp];
        const int SI[4][4] = {{0,1,2,3},{1,4,5,6},{2,5,7,8},{3,6,8,9}};
        double A[4][4], rhs[4];
        for (int k = 0; k < 4; k++){
            for (int l = 0; l < 4; l++) A[k][l] = Hp[SI[k][l]];
            rhs[k] = Jv[k] - Hp[10+k];
        }
        for (int c = 0; c < 4; c++){
            int piv = c; double mx = fabs(A[c][c]);
            for (int rdx = c+1; rdx < 4; rdx++){
                double a_ = fabs(A[rdx][c]);
                if (a_ > mx){ mx = a_; piv = rdx; }
            }
            if (piv != c){
                for (int l = 0; l < 4; l++){ double t = A[c][l]; A[c][l] = A[piv][l]; A[piv][l] = t; }
                double t = rhs[c]; rhs[c] = rhs[piv]; rhs[piv] = t;
            }
            double d = A[c][c];
            for (int rdx = c+1; rdx < 4; rdx++){
                double f = A[rdx][c]/d;
                for (int l = c; l < 4; l++) A[rdx][l] -= f*A[c][l];
                rhs[rdx] -= f*rhs[c];
            }
        }
        double xx[4];
        for (int k = 3; k >= 0; k--){
            double sum = rhs[k];
            for (int l = k+1; l < 4; l++) sum -= A[k][l]*xx[l];
            xx[k] = sum / A[k][k];
        }
        #pragma unroll
        for (int k = 0; k < 4; k++) out[s*4 + k] = (float)xx[k];
    }
}

extern "C" void kernel_launch(void* const* d_in, const int* in_sizes, int n_in,
                              void* d_out, int out_size)
{
    const float* x   = (const float*)d_in[0];
    const float* W0  = (const float*)d_in[1];
    const float* b0  = (const float*)d_in[2];
    const float* g0  = (const float*)d_in[3];
    const float* be0 = (const float*)d_in[4];
    const float* W1  = (const float*)d_in[5];
    const float* b1  = (const float*)d_in[6];
    const float* g1  = (const float*)d_in[7];
    const float* be1 = (const float*)d_in[8];
    const float* W2  = (const float*)d_in[9];
    const float* b2  = (const float*)d_in[10];
    const float* g2  = (const float*)d_in[11];
    const float* be2 = (const float*)d_in[12];
    const float* W3  = (const float*)d_in[13];
    float* out = (float*)d_out;

    int B = in_sizes[0] / 8;
    size_t shmem = 48*sizeof(double) + (size_t)2*NWARP*NV*sizeof(ull)
                 + (size_t)(96 + HD*CP + HD*WPAD)*sizeof(float);
    cudaFuncSetAttribute(lnn_kernel, cudaFuncAttributeMaxDynamicSharedMemorySize, (int)shmem);
    lnn_kernel<<<B, NTHREADS, shmem>>>(x, W0, b0, g0, be0, W1, b1, g1, be1,
                                       W2, b2, g2, be2, W3, out);
}